// round 3
// baseline (speedup 1.0000x reference)
#include <cuda_runtime.h>

// y = min(((x + 1) * 0.75)^2, 10)  — elementwise over 8192*8192 fp32.
// HBM-bound stream: 8 float4 per thread as two MLP-4 batches, streaming
// cache hints (no reuse: 512MB working set vs 126MB L2).
// 67108864 elems = 8192 blocks * 256 thr * 32 elems (exact).

#define T 256u

__device__ __forceinline__ float f(float x) {
    float t = (x + 1.0f) * 0.75f;
    float y = t * t;
    return fminf(y, 10.0f);
}

__device__ __forceinline__ float4 f4(float4 v) {
    float4 r;
    r.x = f(v.x); r.y = f(v.y); r.z = f(v.z); r.w = f(v.w);
    return r;
}

__global__ __launch_bounds__(256) void elemwise_kernel(const float4* __restrict__ in,
                                                       float4* __restrict__ out) {
    unsigned base = blockIdx.x * (T * 8u) + threadIdx.x;

    // Batch 0: 4 independent streaming loads (MLP=4), then streaming stores.
    float4 a0 = __ldcs(&in[base + 0u * T]);
    float4 a1 = __ldcs(&in[base + 1u * T]);
    float4 a2 = __ldcs(&in[base + 2u * T]);
    float4 a3 = __ldcs(&in[base + 3u * T]);
    __stcs(&out[base + 0u * T], f4(a0));
    __stcs(&out[base + 1u * T], f4(a1));
    __stcs(&out[base + 2u * T], f4(a2));
    __stcs(&out[base + 3u * T], f4(a3));

    // Batch 1
    float4 b0 = __ldcs(&in[base + 4u * T]);
    float4 b1 = __ldcs(&in[base + 5u * T]);
    float4 b2 = __ldcs(&in[base + 6u * T]);
    float4 b3 = __ldcs(&in[base + 7u * T]);
    __stcs(&out[base + 4u * T], f4(b0));
    __stcs(&out[base + 5u * T], f4(b1));
    __stcs(&out[base + 6u * T], f4(b2));
    __stcs(&out[base + 7u * T], f4(b3));
}

extern "C" void kernel_launch(void* const* d_in, const int* in_sizes, int n_in,
                              void* d_out, int out_size) {
    const float4* in = (const float4*)d_in[0];
    float4* out = (float4*)d_out;
    int n = in_sizes[0];            // 67108864
    int n4 = n / 4;                 // 16777216 float4s
    int blocks = n4 / (256 * 8);    // 8192, exact
    elemwise_kernel<<<blocks, 256>>>(in, out);
}